// round 13
// baseline (speedup 1.0000x reference)
#include <cuda_runtime.h>

#define FULL 0xffffffffu

typedef unsigned long long u64;

struct C { float x, y; };

// ---------- f32x2 packed helpers ----------
__device__ __forceinline__ u64 PK(float lo, float hi) {
    u64 r;
    asm("mov.b64 %0, {%1, %2};" : "=l"(r)
        : "r"(__float_as_uint(lo)), "r"(__float_as_uint(hi)));
    return r;
}
__device__ __forceinline__ void UPK(u64 p, float& lo, float& hi) {
    unsigned a, b;
    asm("mov.b64 {%0, %1}, %2;" : "=r"(a), "=r"(b) : "l"(p));
    lo = __uint_as_float(a); hi = __uint_as_float(b);
}
__device__ __forceinline__ u64 F2(u64 a, u64 b, u64 c) {
    u64 d;
    asm("fma.rn.f32x2 %0, %1, %2, %3;" : "=l"(d) : "l"(a), "l"(b), "l"(c));
    return d;
}
__device__ __forceinline__ u64 M2(u64 a, u64 b) {
    u64 d;
    asm("mul.rn.f32x2 %0, %1, %2;" : "=l"(d) : "l"(a), "l"(b));
    return d;
}
__device__ __forceinline__ u64 B2(float v) { return PK(v, v); }
__device__ __forceinline__ u64 SW64(u64 p) { float l, h; UPK(p, l, h); return PK(h, l); }
__device__ __forceinline__ u64 SHX64(u64 p, int m) {
    float l, h; UPK(p, l, h);
    return PK(__shfl_xor_sync(FULL, l, m), __shfl_xor_sync(FULL, h, m));
}
__device__ __forceinline__ C cmul(C a, C b) {
    C r;
    r.x = fmaf(a.x, b.x, -a.y * b.y);
    r.y = fmaf(a.x, b.y,  a.y * b.x);
    return r;
}
__device__ __forceinline__ void cmulp(u64& X, u64& Y, C c) {
    u64 cx = B2(c.x), cy = B2(c.y), ny = B2(-c.y);
    u64 nX = F2(cx, X, M2(ny, Y));
    u64 nY = F2(cx, Y, M2(cy, X));
    X = nX; Y = nY;
}

// ---------- precomputed Rot matrices (weight-only, grid-uniform) ----------
__device__ float4 g_U[60];  // SU(2) Rot -> {a.x,a.y,b.x,b.y}

__global__ void prep_kernel(const float* __restrict__ weights) {
    int idx = threadIdx.x;
    if (idx >= 60) return;
    float phi = weights[3 * idx + 0];
    float th  = weights[3 * idx + 1];
    float om  = weights[3 * idx + 2];
    float st, ct, sa, ca, sb, cb;
    __sincosf(0.5f * th,         &st, &ct);
    __sincosf(0.5f * (phi + om), &sa, &ca);
    __sincosf(0.5f * (phi - om), &sb, &cb);
    g_U[idx] = make_float4(ca * ct, -sa * ct, -cb * st, -sb * st);
}

// fused gate coefficients: M = Rot * (RY*RX) in SU(2) form {ga, gb}
__device__ __forceinline__ void buildG(float4 u, C ag, C bg, C& ga, C& gb) {
    const C au{u.x, u.y}, bu{u.z, u.w};
    ga.x = fmaf(au.x, ag.x, fmaf(-au.y, ag.y, fmaf(-bu.x, bg.x, -bu.y * bg.y)));
    ga.y = fmaf(au.x, ag.y, fmaf( au.y, ag.x, fmaf(-bu.y, bg.x,  bu.x * bg.y)));
    gb.x = fmaf(au.x, bg.x, fmaf(-au.y, bg.y, fmaf( bu.x, ag.x,  bu.y * ag.y)));
    gb.y = fmaf(au.x, bg.y, fmaf( au.y, bg.x, fmaf( bu.y, ag.x, -bu.x * ag.y)));
}

// ---------- CNOT ring on packed state ----------
__device__ __forceinline__ void ring(u64 (&X)[16], u64 (&Y)[16],
                                     int srcLo, int srcHi, bool c0) {
#pragma unroll
    for (int k = 0; k < 16; k++)
        if ((k & 8) && !(k & 4)) { u64 t = X[k]; X[k] = X[k ^ 4]; X[k ^ 4] = t;
                                   t = Y[k]; Y[k] = Y[k ^ 4]; Y[k ^ 4] = t; }
#pragma unroll
    for (int k = 0; k < 16; k++)
        if ((k & 4) && !(k & 2)) { u64 t = X[k]; X[k] = X[k ^ 2]; X[k ^ 2] = t;
                                   t = Y[k]; Y[k] = Y[k ^ 2]; Y[k ^ 2] = t; }
#pragma unroll
    for (int k = 0; k < 16; k++)
        if ((k & 2) && !(k & 1)) { u64 t = X[k]; X[k] = X[k ^ 1]; X[k ^ 1] = t;
                                   t = Y[k]; Y[k] = Y[k ^ 1]; Y[k ^ 1] = t; }
#pragma unroll
    for (int k = 0; k < 16; k++) {
        float xl, xh, yl, yh;
        UPK(X[k], xl, xh); UPK(Y[k], yl, yh);
        float nxl, nxh, nyl, nyh;
        if (k & 1) {
            nxl = __shfl_sync(FULL, xh, srcLo); nxh = __shfl_sync(FULL, xl, srcHi);
            nyl = __shfl_sync(FULL, yh, srcLo); nyh = __shfl_sync(FULL, yl, srcHi);
        } else {
            nxl = __shfl_sync(FULL, xl, srcLo); nxh = __shfl_sync(FULL, xh, srcHi);
            nyl = __shfl_sync(FULL, yl, srcLo); nyh = __shfl_sync(FULL, yh, srcHi);
        }
        X[k] = PK(nxl, nxh); Y[k] = PK(nyl, nyh);
    }
#pragma unroll
    for (int k = 0; k < 8; k++) {
        u64 a = X[k], d = X[k + 8];
        X[k] = c0 ? d : a; X[k + 8] = c0 ? a : d;
        a = Y[k]; d = Y[k + 8];
        Y[k] = c0 ? d : a; Y[k + 8] = c0 ? a : d;
    }
}

// ===================== main kernel =====================
// amplitude i = k*64 + h*32 + lane; X[k] packs {Re(h=0),Re(h=1)}, Y imag.
// wire w <-> bit 9-w: w0..w3 -> pack bits 3..0, w4 -> half h, w5..w9 -> lane bits 4..0.
__global__ void __launch_bounds__(192, 3)
qsim_kernel(const float* __restrict__ x,
            const float* __restrict__ post_W,
            const float* __restrict__ post_b,
            const float* __restrict__ readout,
            const float* __restrict__ bias,
            float* __restrict__ out,
            int batch)
{
    const int lane = threadIdx.x & 31;
    const int samp = (int)((blockIdx.x * blockDim.x + threadIdx.x) >> 5);
    if (samp >= batch) return;

    const float x0 = x[2 * samp + 0];
    const float x1 = x[2 * samp + 1];
    float sx0, cx0, sx1, cx1;
    __sincosf(0.5f * x0, &sx0, &cx0);
    __sincosf(0.5f * x1, &sx1, &cx1);

    const C ag   { cx1 * cx0,  sx1 * sx0 };
    const C bg_e { -sx1 * cx0, -cx1 * sx0 };  // even wires: RX(x0), RY(x1)
    const C bg_o { -sx0 * cx1, -cx0 * sx1 };  // odd  wires: RX(x1), RY(x0)

    int gsrc = lane;
    gsrc = (gsrc & 2)  ? (gsrc ^ 1) : gsrc;
    gsrc = (gsrc & 4)  ? (gsrc ^ 2) : gsrc;
    gsrc = (gsrc & 8)  ? (gsrc ^ 4) : gsrc;
    gsrc = (gsrc & 16) ? (gsrc ^ 8) : gsrc;
    const int srcLo = gsrc, srcHi = gsrc ^ 16;
    const bool c0 = (lane & 1) != 0;

    // Which gate this lane builds (layers 1..5); lanes >= 10 duplicate gate 9.
    const int myw = lane < 10 ? lane : 9;
    const C myBg = (myw & 1) ? bg_o : bg_e;

    u64 X[16], Y[16];

    // ======== layer 0: product state, gates built on demand (low reg peak) ====
    {
        C ga, gb, f;
        buildG(g_U[5], ag, bg_o, ga, gb);
        C Lc = ((lane >> 4) & 1) ? C{-gb.x, gb.y} : ga;
        buildG(g_U[6], ag, bg_e, ga, gb);
        f = ((lane >> 3) & 1) ? C{-gb.x, gb.y} : ga;  Lc = cmul(Lc, f);
        buildG(g_U[7], ag, bg_o, ga, gb);
        f = ((lane >> 2) & 1) ? C{-gb.x, gb.y} : ga;  Lc = cmul(Lc, f);
        buildG(g_U[8], ag, bg_e, ga, gb);
        f = ((lane >> 1) & 1) ? C{-gb.x, gb.y} : ga;  Lc = cmul(Lc, f);
        buildG(g_U[9], ag, bg_o, ga, gb);
        f = ( lane       & 1) ? C{-gb.x, gb.y} : ga;  Lc = cmul(Lc, f);
        buildG(g_U[4], ag, bg_e, ga, gb);
        C h0 = cmul(Lc, ga);
        C h1 = cmul(Lc, C{-gb.x, gb.y});
        X[0] = PK(h0.x, h1.x);
        Y[0] = PK(h0.y, h1.y);
        buildG(g_U[3], ag, bg_o, ga, gb);
        X[1] = X[0]; Y[1] = Y[0];
        cmulp(X[0], Y[0], ga); cmulp(X[1], Y[1], C{-gb.x, gb.y});
        buildG(g_U[2], ag, bg_e, ga, gb);
#pragma unroll
        for (int k = 0; k < 2; k++) {
            X[k + 2] = X[k]; Y[k + 2] = Y[k];
            cmulp(X[k], Y[k], ga); cmulp(X[k + 2], Y[k + 2], C{-gb.x, gb.y});
        }
        buildG(g_U[1], ag, bg_o, ga, gb);
#pragma unroll
        for (int k = 0; k < 4; k++) {
            X[k + 4] = X[k]; Y[k + 4] = Y[k];
            cmulp(X[k], Y[k], ga); cmulp(X[k + 4], Y[k + 4], C{-gb.x, gb.y});
        }
        buildG(g_U[0], ag, bg_e, ga, gb);
#pragma unroll
        for (int k = 0; k < 8; k++) {
            X[k + 8] = X[k]; Y[k + 8] = Y[k];
            cmulp(X[k], Y[k], ga); cmulp(X[k + 8], Y[k + 8], C{-gb.x, gb.y});
        }
    }
    ring(X, Y, srcLo, srcHi, c0);

    // ======== layers 1..5: distributed gate build + butterflies ========
#pragma unroll 1
    for (int layer = 1; layer < 6; layer++) {
        const float4* Ul = g_U + layer * 10;

        C myga, mygb;
        buildG(Ul[myw], ag, myBg, myga, mygb);

#pragma unroll
        for (int w = 0; w < 10; w++) {
            const float gax = __shfl_sync(FULL, myga.x, w);
            const float gay = __shfl_sync(FULL, myga.y, w);
            const float gbx = __shfl_sync(FULL, mygb.x, w);
            const float gby = __shfl_sync(FULL, mygb.y, w);

            if (w <= 3) {
                const int ks = 8 >> w;
                const u64 paxx = B2(gax), pnay = B2(-gay), ppay = B2(gay);
                const u64 pbxx = B2(gbx), pnbx = B2(-gbx);
                const u64 pnby = B2(-gby), ppby = B2(gby);
#pragma unroll
                for (int kl = 0; kl < 16; kl++) {
                    if (kl & ks) continue;
                    const int kh = kl | ks;
                    u64 Xl = X[kl], Yl = Y[kl], Xh = X[kh], Yh = Y[kh];
                    X[kl] = F2(paxx, Xl, F2(pnay, Yl, F2(pbxx, Xh, M2(pnby, Yh))));
                    Y[kl] = F2(paxx, Yl, F2(ppay, Xl, F2(pbxx, Yh, M2(ppby, Xh))));
                    X[kh] = F2(paxx, Xh, F2(ppay, Yh, F2(pnbx, Xl, M2(pnby, Yl))));
                    Y[kh] = F2(paxx, Yh, F2(pnay, Xh, F2(pnbx, Yl, M2(ppby, Xl))));
                }
            } else if (w == 4) {
                const u64 qaxx = B2(gax);
                const u64 qay  = PK(-gay,  gay);
                const u64 qay2 = PK( gay, -gay);
                const u64 qbx  = PK( gbx, -gbx);
                const u64 qnby = B2(-gby), qpby = B2(gby);
#pragma unroll
                for (int k = 0; k < 16; k++) {
                    u64 ownX = F2(qaxx, X[k], M2(qay,  Y[k]));
                    u64 ownY = F2(qaxx, Y[k], M2(qay2, X[k]));
                    u64 Xs = SW64(X[k]), Ys = SW64(Y[k]);
                    u64 nX = F2(qbx, Xs, F2(qnby, Ys, ownX));
                    u64 nY = F2(qbx, Ys, F2(qpby, Xs, ownY));
                    X[k] = nX; Y[k] = nY;
                }
            } else {
                const int m = 1 << (9 - w);
                const bool hib = (lane & m) != 0;
                const float aly = hib ? -gay : gay;
                const float bex = hib ? -gbx : gbx;
                const u64 pA   = B2(gax);
                const u64 pAy  = B2(aly),  pnAy = B2(-aly);
                const u64 pBx  = B2(bex);
                const u64 pBy  = B2(gby), pnBy = B2(-gby);
#pragma unroll
                for (int k = 0; k < 16; k++) {
                    u64 ownX = F2(pA, X[k], M2(pnAy, Y[k]));
                    u64 ownY = F2(pA, Y[k], M2(pAy,  X[k]));
                    u64 OX = SHX64(X[k], m), OY = SHX64(Y[k], m);
                    u64 nX = F2(pBx, OX, F2(pnBy, OY, ownX));
                    u64 nY = F2(pBx, OY, F2(pBy,  OX, ownY));
                    X[k] = nX; Y[k] = nY;
                }
            }
        }

        ring(X, Y, srcLo, srcHi, c0);
    }

    // ---- readout ----
    float pw[10];
#pragma unroll
    for (int w = 0; w < 10; w++) pw[w] = post_W[w];

    float laneCoef = 0.f;
#pragma unroll
    for (int w = 5; w < 10; w++)
        laneCoef += ((lane >> (9 - w)) & 1) ? -pw[w] : pw[w];

    u64 acc2 = 0ull;
#pragma unroll
    for (int k = 0; k < 16; k++) {
        float base = laneCoef;
#pragma unroll
        for (int w = 0; w < 4; w++)
            base += ((k >> (3 - w)) & 1) ? -pw[w] : pw[w];
        const u64 cp = PK(base + pw[4], base - pw[4]);
        const u64 p2 = F2(X[k], X[k], M2(Y[k], Y[k]));
        acc2 = F2(p2, cp, acc2);
    }
    float aLo, aHi;
    UPK(acc2, aLo, aHi);
    float acc = aLo + aHi;

#pragma unroll
    for (int off = 16; off; off >>= 1)
        acc += __shfl_xor_sync(FULL, acc, off);

    if (lane == 0)
        out[samp] = readout[0] * (acc + post_b[0]) + bias[0];
}

extern "C" void kernel_launch(void* const* d_in, const int* in_sizes, int n_in,
                              void* d_out, int out_size)
{
    const float* x       = (const float*)d_in[0];
    const float* weights = (const float*)d_in[1];
    const float* post_W  = (const float*)d_in[2];
    const float* post_b  = (const float*)d_in[3];
    const float* readout = (const float*)d_in[4];
    const float* bias    = (const float*)d_in[5];
    float* out = (float*)d_out;

    const int batch = in_sizes[0] / 2;
    prep_kernel<<<1, 64>>>(weights);

    const int threads = 192;   // 6 warps/block, 3 blocks/SM -> 18 warps/SM
    const int total_threads = batch * 32;
    const int blocks = (total_threads + threads - 1) / threads;
    qsim_kernel<<<blocks, threads>>>(x, post_W, post_b, readout, bias, out, batch);
}

// round 14
// speedup vs baseline: 1.1002x; 1.1002x over previous
#include <cuda_runtime.h>

#define FULL 0xffffffffu

typedef unsigned long long u64;

struct C { float x, y; };

// ---------- f32x2 packed helpers ----------
__device__ __forceinline__ u64 PK(float lo, float hi) {
    u64 r;
    asm("mov.b64 %0, {%1, %2};" : "=l"(r)
        : "r"(__float_as_uint(lo)), "r"(__float_as_uint(hi)));
    return r;
}
__device__ __forceinline__ void UPK(u64 p, float& lo, float& hi) {
    unsigned a, b;
    asm("mov.b64 {%0, %1}, %2;" : "=r"(a), "=r"(b) : "l"(p));
    lo = __uint_as_float(a); hi = __uint_as_float(b);
}
__device__ __forceinline__ u64 F2(u64 a, u64 b, u64 c) {
    u64 d;
    asm("fma.rn.f32x2 %0, %1, %2, %3;" : "=l"(d) : "l"(a), "l"(b), "l"(c));
    return d;
}
__device__ __forceinline__ u64 M2(u64 a, u64 b) {
    u64 d;
    asm("mul.rn.f32x2 %0, %1, %2;" : "=l"(d) : "l"(a), "l"(b));
    return d;
}
__device__ __forceinline__ u64 B2(float v) { return PK(v, v); }
__device__ __forceinline__ u64 SW64(u64 p) { float l, h; UPK(p, l, h); return PK(h, l); }
__device__ __forceinline__ u64 SHX64(u64 p, int m) {
    float l, h; UPK(p, l, h);
    return PK(__shfl_xor_sync(FULL, l, m), __shfl_xor_sync(FULL, h, m));
}
__device__ __forceinline__ C cmul(C a, C b) {
    C r;
    r.x = fmaf(a.x, b.x, -a.y * b.y);
    r.y = fmaf(a.x, b.y,  a.y * b.x);
    return r;
}
__device__ __forceinline__ void cmulp(u64& X, u64& Y, C c) {
    u64 cx = B2(c.x), cy = B2(c.y), ny = B2(-c.y);
    u64 nX = F2(cx, X, M2(ny, Y));
    u64 nY = F2(cx, Y, M2(cy, X));
    X = nX; Y = nY;
}

// ---------- precomputed Rot matrices (weight-only, grid-uniform) ----------
__device__ float4 g_U[60];  // SU(2) Rot -> {a.x,a.y,b.x,b.y}

__global__ void prep_kernel(const float* __restrict__ weights) {
    int idx = threadIdx.x;
    if (idx >= 60) return;
    float phi = weights[3 * idx + 0];
    float th  = weights[3 * idx + 1];
    float om  = weights[3 * idx + 2];
    float st, ct, sa, ca, sb, cb;
    __sincosf(0.5f * th,         &st, &ct);
    __sincosf(0.5f * (phi + om), &sa, &ca);
    __sincosf(0.5f * (phi - om), &sb, &cb);
    g_U[idx] = make_float4(ca * ct, -sa * ct, -cb * st, -sb * st);
}

// fused gate coefficients: M = Rot * (RY*RX) in SU(2) form {ga, gb}
__device__ __forceinline__ void buildG(float4 u, C ag, C bg, C& ga, C& gb) {
    const C au{u.x, u.y}, bu{u.z, u.w};
    ga.x = fmaf(au.x, ag.x, fmaf(-au.y, ag.y, fmaf(-bu.x, bg.x, -bu.y * bg.y)));
    ga.y = fmaf(au.x, ag.y, fmaf( au.y, ag.x, fmaf(-bu.y, bg.x,  bu.x * bg.y)));
    gb.x = fmaf(au.x, bg.x, fmaf(-au.y, bg.y, fmaf( bu.x, ag.x,  bu.y * ag.y)));
    gb.y = fmaf(au.x, bg.y, fmaf( au.y, bg.x, fmaf( bu.y, ag.x, -bu.x * ag.y)));
}

// ---------- CNOT ring on packed state ----------
__device__ __forceinline__ void ring(u64 (&X)[16], u64 (&Y)[16],
                                     int srcLo, int srcHi, bool c0) {
#pragma unroll
    for (int k = 0; k < 16; k++)
        if ((k & 8) && !(k & 4)) { u64 t = X[k]; X[k] = X[k ^ 4]; X[k ^ 4] = t;
                                   t = Y[k]; Y[k] = Y[k ^ 4]; Y[k ^ 4] = t; }
#pragma unroll
    for (int k = 0; k < 16; k++)
        if ((k & 4) && !(k & 2)) { u64 t = X[k]; X[k] = X[k ^ 2]; X[k ^ 2] = t;
                                   t = Y[k]; Y[k] = Y[k ^ 2]; Y[k ^ 2] = t; }
#pragma unroll
    for (int k = 0; k < 16; k++)
        if ((k & 2) && !(k & 1)) { u64 t = X[k]; X[k] = X[k ^ 1]; X[k ^ 1] = t;
                                   t = Y[k]; Y[k] = Y[k ^ 1]; Y[k ^ 1] = t; }
#pragma unroll
    for (int k = 0; k < 16; k++) {
        float xl, xh, yl, yh;
        UPK(X[k], xl, xh); UPK(Y[k], yl, yh);
        float nxl, nxh, nyl, nyh;
        if (k & 1) {
            nxl = __shfl_sync(FULL, xh, srcLo); nxh = __shfl_sync(FULL, xl, srcHi);
            nyl = __shfl_sync(FULL, yh, srcLo); nyh = __shfl_sync(FULL, yl, srcHi);
        } else {
            nxl = __shfl_sync(FULL, xl, srcLo); nxh = __shfl_sync(FULL, xh, srcHi);
            nyl = __shfl_sync(FULL, yl, srcLo); nyh = __shfl_sync(FULL, yh, srcHi);
        }
        X[k] = PK(nxl, nxh); Y[k] = PK(nyl, nyh);
    }
#pragma unroll
    for (int k = 0; k < 8; k++) {
        u64 a = X[k], d = X[k + 8];
        X[k] = c0 ? d : a; X[k + 8] = c0 ? a : d;
        a = Y[k]; d = Y[k + 8];
        Y[k] = c0 ? d : a; Y[k + 8] = c0 ? a : d;
    }
}

// compile-time parity helper
__host__ __device__ constexpr int par4(int v) { return ((v >> 3) ^ (v >> 2) ^ (v >> 1) ^ v) & 1; }

// ===================== main kernel =====================
// amplitude i = (k<<6) | (h<<5) | lane; X[k] packs {Re(h=0),Re(h=1)}, Y imag.
// wire w <-> bit 9-w: w0..w3 -> pack bits 3..0, w4 -> half h, w5..w9 -> lane bits 4..0.
__global__ void __launch_bounds__(256, 2)
qsim_kernel(const float* __restrict__ x,
            const float* __restrict__ post_W,
            const float* __restrict__ post_b,
            const float* __restrict__ readout,
            const float* __restrict__ bias,
            float* __restrict__ out,
            int batch)
{
    const int lane = threadIdx.x & 31;
    const int samp = (int)((blockIdx.x * blockDim.x + threadIdx.x) >> 5);
    if (samp >= batch) return;

    const float x0 = x[2 * samp + 0];
    const float x1 = x[2 * samp + 1];
    float sx0, cx0, sx1, cx1;
    __sincosf(0.5f * x0, &sx0, &cx0);
    __sincosf(0.5f * x1, &sx1, &cx1);

    const C ag   { cx1 * cx0,  sx1 * sx0 };
    const C bg_e { -sx1 * cx0, -cx1 * sx0 };  // even wires: RX(x0), RY(x1)
    const C bg_o { -sx0 * cx1, -cx0 * sx1 };  // odd  wires: RX(x1), RY(x0)

    int gsrc = lane;
    gsrc = (gsrc & 2)  ? (gsrc ^ 1) : gsrc;
    gsrc = (gsrc & 4)  ? (gsrc ^ 2) : gsrc;
    gsrc = (gsrc & 8)  ? (gsrc ^ 4) : gsrc;
    gsrc = (gsrc & 16) ? (gsrc ^ 8) : gsrc;
    const int srcLo = gsrc, srcHi = gsrc ^ 16;
    const bool c0 = (lane & 1) != 0;

    // Which gate this lane builds (layers 1..5); lanes >= 10 duplicate gate 9.
    const int myw = lane < 10 ? lane : 9;
    const C myBg = (myw & 1) ? bg_o : bg_e;

    u64 X[16], Y[16];

    // ======== layer 0: product state, gates built on demand ========
    {
        C ga, gb, f;
        buildG(g_U[5], ag, bg_o, ga, gb);
        C Lc = ((lane >> 4) & 1) ? C{-gb.x, gb.y} : ga;
        buildG(g_U[6], ag, bg_e, ga, gb);
        f = ((lane >> 3) & 1) ? C{-gb.x, gb.y} : ga;  Lc = cmul(Lc, f);
        buildG(g_U[7], ag, bg_o, ga, gb);
        f = ((lane >> 2) & 1) ? C{-gb.x, gb.y} : ga;  Lc = cmul(Lc, f);
        buildG(g_U[8], ag, bg_e, ga, gb);
        f = ((lane >> 1) & 1) ? C{-gb.x, gb.y} : ga;  Lc = cmul(Lc, f);
        buildG(g_U[9], ag, bg_o, ga, gb);
        f = ( lane       & 1) ? C{-gb.x, gb.y} : ga;  Lc = cmul(Lc, f);
        buildG(g_U[4], ag, bg_e, ga, gb);
        C h0 = cmul(Lc, ga);
        C h1 = cmul(Lc, C{-gb.x, gb.y});
        X[0] = PK(h0.x, h1.x);
        Y[0] = PK(h0.y, h1.y);
        buildG(g_U[3], ag, bg_o, ga, gb);
        X[1] = X[0]; Y[1] = Y[0];
        cmulp(X[0], Y[0], ga); cmulp(X[1], Y[1], C{-gb.x, gb.y});
        buildG(g_U[2], ag, bg_e, ga, gb);
#pragma unroll
        for (int k = 0; k < 2; k++) {
            X[k + 2] = X[k]; Y[k + 2] = Y[k];
            cmulp(X[k], Y[k], ga); cmulp(X[k + 2], Y[k + 2], C{-gb.x, gb.y});
        }
        buildG(g_U[1], ag, bg_o, ga, gb);
#pragma unroll
        for (int k = 0; k < 4; k++) {
            X[k + 4] = X[k]; Y[k + 4] = Y[k];
            cmulp(X[k], Y[k], ga); cmulp(X[k + 4], Y[k + 4], C{-gb.x, gb.y});
        }
        buildG(g_U[0], ag, bg_e, ga, gb);
#pragma unroll
        for (int k = 0; k < 8; k++) {
            X[k + 8] = X[k]; Y[k + 8] = Y[k];
            cmulp(X[k], Y[k], ga); cmulp(X[k + 8], Y[k + 8], C{-gb.x, gb.y});
        }
    }

    // ======== layers 1..5: ring first, then gates; final ring folded into readout
#pragma unroll 1
    for (int layer = 1; layer < 6; layer++) {
        ring(X, Y, srcLo, srcHi, c0);

        const float4* Ul = g_U + layer * 10;
        C myga, mygb;
        buildG(Ul[myw], ag, myBg, myga, mygb);

#pragma unroll
        for (int w = 0; w < 10; w++) {
            const float gax = __shfl_sync(FULL, myga.x, w);
            const float gay = __shfl_sync(FULL, myga.y, w);
            const float gbx = __shfl_sync(FULL, mygb.x, w);
            const float gby = __shfl_sync(FULL, mygb.y, w);

            if (w <= 3) {
                const int ks = 8 >> w;
                const u64 paxx = B2(gax), pnay = B2(-gay), ppay = B2(gay);
                const u64 pbxx = B2(gbx), pnbx = B2(-gbx);
                const u64 pnby = B2(-gby), ppby = B2(gby);
#pragma unroll
                for (int kl = 0; kl < 16; kl++) {
                    if (kl & ks) continue;
                    const int kh = kl | ks;
                    u64 Xl = X[kl], Yl = Y[kl], Xh = X[kh], Yh = Y[kh];
                    X[kl] = F2(paxx, Xl, F2(pnay, Yl, F2(pbxx, Xh, M2(pnby, Yh))));
                    Y[kl] = F2(paxx, Yl, F2(ppay, Xl, F2(pbxx, Yh, M2(ppby, Xh))));
                    X[kh] = F2(paxx, Xh, F2(ppay, Yh, F2(pnbx, Xl, M2(pnby, Yl))));
                    Y[kh] = F2(paxx, Yh, F2(pnay, Xh, F2(pnbx, Yl, M2(ppby, Xl))));
                }
            } else if (w == 4) {
                const u64 qaxx = B2(gax);
                const u64 qay  = PK(-gay,  gay);
                const u64 qay2 = PK( gay, -gay);
                const u64 qbx  = PK( gbx, -gbx);
                const u64 qnby = B2(-gby), qpby = B2(gby);
#pragma unroll
                for (int k = 0; k < 16; k++) {
                    u64 ownX = F2(qaxx, X[k], M2(qay,  Y[k]));
                    u64 ownY = F2(qaxx, Y[k], M2(qay2, X[k]));
                    u64 Xs = SW64(X[k]), Ys = SW64(Y[k]);
                    u64 nX = F2(qbx, Xs, F2(qnby, Ys, ownX));
                    u64 nY = F2(qbx, Ys, F2(qpby, Xs, ownY));
                    X[k] = nX; Y[k] = nY;
                }
            } else {
                const int m = 1 << (9 - w);
                const bool hib = (lane & m) != 0;
                const float aly = hib ? -gay : gay;
                const float bex = hib ? -gbx : gbx;
                const u64 pA   = B2(gax);
                const u64 pAy  = B2(aly),  pnAy = B2(-aly);
                const u64 pBx  = B2(bex);
                const u64 pBy  = B2(gby), pnBy = B2(-gby);
#pragma unroll
                for (int k = 0; k < 16; k++) {
                    u64 ownX = F2(pA, X[k], M2(pnAy, Y[k]));
                    u64 ownY = F2(pA, Y[k], M2(pAy,  X[k]));
                    u64 OX = SHX64(X[k], m), OY = SHX64(Y[k], m);
                    u64 nX = F2(pBx, OX, F2(pnBy, OY, ownX));
                    u64 nY = F2(pBx, OY, F2(pBy,  OX, ownY));
                    X[k] = nX; Y[k] = nY;
                }
            }
        }
    }

    // ---- readout with final CNOT ring folded in ----
    // coef_w(i) = (-1)^{parity(M_w & i)}, M_w = row_{9-w}(R):
    //   M_0 = 0x1FF;  M_w = 0x3FF & ~((1<<(9-w))-1)  for w>=1.
    // Decompose M over i = (k<<6)|(h<<5)|lane:
    //   lane masks: w0:0x1F  w5:0x10 w6:0x18 w7:0x1C w8:0x1E w9:0x1F  (w1..4: 0)
    //   h bit:      set for w in {0,4,5,6,7,8,9}
    //   k masks:    w0:7  w1:12  w2:14  w3..9:15
    float pw[10];
#pragma unroll
    for (int w = 0; w < 10; w++) pw[w] = post_W[w];

    const float t0 = (__popc(lane & 0x1F) & 1) ? -pw[0] : pw[0];
    const float t5 = (__popc(lane & 0x10) & 1) ? -pw[5] : pw[5];
    const float t6 = (__popc(lane & 0x18) & 1) ? -pw[6] : pw[6];
    const float t7 = (__popc(lane & 0x1C) & 1) ? -pw[7] : pw[7];
    const float t8 = (__popc(lane & 0x1E) & 1) ? -pw[8] : pw[8];
    const float t9 = (__popc(lane & 0x1F) & 1) ? -pw[9] : pw[9];
    const float S  = pw[4] + t5 + t6 + t7 + t8 + t9;  // w4..w9: h-flipped, kσ = par(k)
    const float Pp = pw[3] + S;   // lo: σp * (t3 + S)
    const float Qm = pw[3] - S;   // hi: σp * (t3 - S)

    u64 acc2 = 0ull;
#pragma unroll
    for (int k = 0; k < 16; k++) {
        const float s1 = par4(k & 12) ? -1.f : 1.f;   // w1
        const float s2 = par4(k & 14) ? -1.f : 1.f;   // w2
        const float sp = par4(k)      ? -1.f : 1.f;   // w3..w9
        const float s0 = par4(k & 7)  ? -1.f : 1.f;   // w0
        const float common = s1 * pw[1] + s2 * pw[2];
        const float lo = common + sp * Pp + s0 * t0;
        const float hi = common + sp * Qm - s0 * t0;
        const u64 cp = PK(lo, hi);
        const u64 p2 = F2(X[k], X[k], M2(Y[k], Y[k]));
        acc2 = F2(p2, cp, acc2);
    }
    float aLo, aHi;
    UPK(acc2, aLo, aHi);
    float acc = aLo + aHi;

#pragma unroll
    for (int off = 16; off; off >>= 1)
        acc += __shfl_xor_sync(FULL, acc, off);

    if (lane == 0)
        out[samp] = readout[0] * (acc + post_b[0]) + bias[0];
}

extern "C" void kernel_launch(void* const* d_in, const int* in_sizes, int n_in,
                              void* d_out, int out_size)
{
    const float* x       = (const float*)d_in[0];
    const float* weights = (const float*)d_in[1];
    const float* post_W  = (const float*)d_in[2];
    const float* post_b  = (const float*)d_in[3];
    const float* readout = (const float*)d_in[4];
    const float* bias    = (const float*)d_in[5];
    float* out = (float*)d_out;

    const int batch = in_sizes[0] / 2;
    prep_kernel<<<1, 64>>>(weights);

    const int threads = 256;   // 8 warps/block, 2 blocks/SM -> 16 warps/SM
    const int total_threads = batch * 32;
    const int blocks = (total_threads + threads - 1) / threads;
    qsim_kernel<<<blocks, threads>>>(x, post_W, post_b, readout, bias, out, batch);
}

// round 15
// speedup vs baseline: 1.1192x; 1.0172x over previous
#include <cuda_runtime.h>

#define FULL 0xffffffffu

typedef unsigned long long u64;

struct C { float x, y; };

// ---------- f32x2 packed helpers ----------
__device__ __forceinline__ u64 PK(float lo, float hi) {
    u64 r;
    asm("mov.b64 %0, {%1, %2};" : "=l"(r)
        : "r"(__float_as_uint(lo)), "r"(__float_as_uint(hi)));
    return r;
}
__device__ __forceinline__ void UPK(u64 p, float& lo, float& hi) {
    unsigned a, b;
    asm("mov.b64 {%0, %1}, %2;" : "=r"(a), "=r"(b) : "l"(p));
    lo = __uint_as_float(a); hi = __uint_as_float(b);
}
__device__ __forceinline__ u64 F2(u64 a, u64 b, u64 c) {
    u64 d;
    asm("fma.rn.f32x2 %0, %1, %2, %3;" : "=l"(d) : "l"(a), "l"(b), "l"(c));
    return d;
}
__device__ __forceinline__ u64 M2(u64 a, u64 b) {
    u64 d;
    asm("mul.rn.f32x2 %0, %1, %2;" : "=l"(d) : "l"(a), "l"(b));
    return d;
}
__device__ __forceinline__ u64 B2(float v) { return PK(v, v); }
__device__ __forceinline__ u64 SW64(u64 p) { float l, h; UPK(p, l, h); return PK(h, l); }
__device__ __forceinline__ u64 SHX64(u64 p, int m) {
    float l, h; UPK(p, l, h);
    return PK(__shfl_xor_sync(FULL, l, m), __shfl_xor_sync(FULL, h, m));
}
__device__ __forceinline__ C cmul(C a, C b) {
    C r;
    r.x = fmaf(a.x, b.x, -a.y * b.y);
    r.y = fmaf(a.x, b.y,  a.y * b.x);
    return r;
}
__device__ __forceinline__ void cmulp(u64& X, u64& Y, C c) {
    u64 cx = B2(c.x), cy = B2(c.y), ny = B2(-c.y);
    u64 nX = F2(cx, X, M2(ny, Y));
    u64 nY = F2(cx, Y, M2(cy, X));
    X = nX; Y = nY;
}

// Rot gate (SU(2)) from raw weights: a = e^{-i(phi+om)/2} cos(th/2), b = -e^{i(phi-om)/2} sin(th/2)
__device__ __forceinline__ void buildRot(const float* __restrict__ wl, C& au, C& bu) {
    const float phi = wl[0], th = wl[1], om = wl[2];
    float st, ct, sa, ca, sb, cb;
    __sincosf(0.5f * th,         &st, &ct);
    __sincosf(0.5f * (phi + om), &sa, &ca);
    __sincosf(0.5f * (phi - om), &sb, &cb);
    au = C{ ca * ct, -sa * ct };
    bu = C{ -cb * st, -sb * st };
}

// fused gate coefficients: M = Rot * (RY*RX) in SU(2) form {ga, gb}
__device__ __forceinline__ void buildG(C au, C bu, C ag, C bg, C& ga, C& gb) {
    ga.x = fmaf(au.x, ag.x, fmaf(-au.y, ag.y, fmaf(-bu.x, bg.x, -bu.y * bg.y)));
    ga.y = fmaf(au.x, ag.y, fmaf( au.y, ag.x, fmaf(-bu.y, bg.x,  bu.x * bg.y)));
    gb.x = fmaf(au.x, bg.x, fmaf(-au.y, bg.y, fmaf( bu.x, ag.x,  bu.y * ag.y)));
    gb.y = fmaf(au.x, bg.y, fmaf( au.y, bg.x, fmaf( bu.y, ag.x, -bu.x * ag.y)));
}

// ---------- CNOT ring on packed state ----------
__device__ __forceinline__ void ring(u64 (&X)[16], u64 (&Y)[16],
                                     int srcLo, int srcHi, bool c0) {
#pragma unroll
    for (int k = 0; k < 16; k++)
        if ((k & 8) && !(k & 4)) { u64 t = X[k]; X[k] = X[k ^ 4]; X[k ^ 4] = t;
                                   t = Y[k]; Y[k] = Y[k ^ 4]; Y[k ^ 4] = t; }
#pragma unroll
    for (int k = 0; k < 16; k++)
        if ((k & 4) && !(k & 2)) { u64 t = X[k]; X[k] = X[k ^ 2]; X[k ^ 2] = t;
                                   t = Y[k]; Y[k] = Y[k ^ 2]; Y[k ^ 2] = t; }
#pragma unroll
    for (int k = 0; k < 16; k++)
        if ((k & 2) && !(k & 1)) { u64 t = X[k]; X[k] = X[k ^ 1]; X[k ^ 1] = t;
                                   t = Y[k]; Y[k] = Y[k ^ 1]; Y[k ^ 1] = t; }
#pragma unroll
    for (int k = 0; k < 16; k++) {
        float xl, xh, yl, yh;
        UPK(X[k], xl, xh); UPK(Y[k], yl, yh);
        float nxl, nxh, nyl, nyh;
        if (k & 1) {
            nxl = __shfl_sync(FULL, xh, srcLo); nxh = __shfl_sync(FULL, xl, srcHi);
            nyl = __shfl_sync(FULL, yh, srcLo); nyh = __shfl_sync(FULL, yl, srcHi);
        } else {
            nxl = __shfl_sync(FULL, xl, srcLo); nxh = __shfl_sync(FULL, xh, srcHi);
            nyl = __shfl_sync(FULL, yl, srcLo); nyh = __shfl_sync(FULL, yh, srcHi);
        }
        X[k] = PK(nxl, nxh); Y[k] = PK(nyl, nyh);
    }
#pragma unroll
    for (int k = 0; k < 8; k++) {
        u64 a = X[k], d = X[k + 8];
        X[k] = c0 ? d : a; X[k + 8] = c0 ? a : d;
        a = Y[k]; d = Y[k + 8];
        Y[k] = c0 ? d : a; Y[k + 8] = c0 ? a : d;
    }
}

// compile-time parity helper
__host__ __device__ constexpr int par4(int v) { return ((v >> 3) ^ (v >> 2) ^ (v >> 1) ^ v) & 1; }

// ===================== main kernel =====================
// amplitude i = (k<<6) | (h<<5) | lane; X[k] packs {Re(h=0),Re(h=1)}, Y imag.
// wire w <-> bit 9-w: w0..w3 -> pack bits 3..0, w4 -> half h, w5..w9 -> lane bits 4..0.
__global__ void __launch_bounds__(256, 2)
qsim_kernel(const float* __restrict__ x,
            const float* __restrict__ weights,
            const float* __restrict__ post_W,
            const float* __restrict__ post_b,
            const float* __restrict__ readout,
            const float* __restrict__ bias,
            float* __restrict__ out,
            int batch)
{
    const int lane = threadIdx.x & 31;
    const int samp = (int)((blockIdx.x * blockDim.x + threadIdx.x) >> 5);
    if (samp >= batch) return;

    const float x0 = x[2 * samp + 0];
    const float x1 = x[2 * samp + 1];
    float sx0, cx0, sx1, cx1;
    __sincosf(0.5f * x0, &sx0, &cx0);
    __sincosf(0.5f * x1, &sx1, &cx1);

    const C ag   { cx1 * cx0,  sx1 * sx0 };
    const C bg_e { -sx1 * cx0, -cx1 * sx0 };  // even wires: RX(x0), RY(x1)
    const C bg_o { -sx0 * cx1, -cx0 * sx1 };  // odd  wires: RX(x1), RY(x0)

    int gsrc = lane;
    gsrc = (gsrc & 2)  ? (gsrc ^ 1) : gsrc;
    gsrc = (gsrc & 4)  ? (gsrc ^ 2) : gsrc;
    gsrc = (gsrc & 8)  ? (gsrc ^ 4) : gsrc;
    gsrc = (gsrc & 16) ? (gsrc ^ 8) : gsrc;
    const int srcLo = gsrc, srcHi = gsrc ^ 16;
    const bool c0 = (lane & 1) != 0;

    // Which gate this lane builds; lanes >= 10 duplicate gate 9.
    const int myw = lane < 10 ? lane : 9;
    const C myBg = (myw & 1) ? bg_o : bg_e;

    u64 X[16], Y[16];

    // ======== layer 0: product state; distributed builds + broadcasts ========
    {
        C au, bu, g0a, g0b;
        buildRot(weights + myw * 3, au, bu);
        buildG(au, bu, ag, myBg, g0a, g0b);

        // lane factor: wires 5..9 selected by lane bits 4..0
        C Lc;
        {
            const float gax = __shfl_sync(FULL, g0a.x, 5);
            const float gay = __shfl_sync(FULL, g0a.y, 5);
            const float gbx = __shfl_sync(FULL, g0b.x, 5);
            const float gby = __shfl_sync(FULL, g0b.y, 5);
            Lc = ((lane >> 4) & 1) ? C{-gbx, gby} : C{gax, gay};
        }
#pragma unroll
        for (int wv = 6; wv <= 9; wv++) {
            const float gax = __shfl_sync(FULL, g0a.x, wv);
            const float gay = __shfl_sync(FULL, g0a.y, wv);
            const float gbx = __shfl_sync(FULL, g0b.x, wv);
            const float gby = __shfl_sync(FULL, g0b.y, wv);
            const C f = ((lane >> (9 - wv)) & 1) ? C{-gbx, gby} : C{gax, gay};
            Lc = cmul(Lc, f);
        }
        // half factor (wire 4)
        {
            const float gax = __shfl_sync(FULL, g0a.x, 4);
            const float gay = __shfl_sync(FULL, g0a.y, 4);
            const float gbx = __shfl_sync(FULL, g0b.x, 4);
            const float gby = __shfl_sync(FULL, g0b.y, 4);
            C h0 = cmul(Lc, C{gax, gay});
            C h1 = cmul(Lc, C{-gbx, gby});
            X[0] = PK(h0.x, h1.x);
            Y[0] = PK(h0.y, h1.y);
        }
        // tensor tree over pack bits: bit0=wire3, bit1=wire2, bit2=wire1, bit3=wire0
#pragma unroll
        for (int wv = 3; wv >= 0; wv--) {
            const float gax = __shfl_sync(FULL, g0a.x, wv);
            const float gay = __shfl_sync(FULL, g0a.y, wv);
            const float gbx = __shfl_sync(FULL, g0b.x, wv);
            const float gby = __shfl_sync(FULL, g0b.y, wv);
            const C f0{gax, gay}, f1{-gbx, gby};
            const int n = 1 << (3 - wv);
#pragma unroll
            for (int k = 0; k < 8; k++) {
                if (k >= n) break;
                X[k + n] = X[k]; Y[k + n] = Y[k];
                cmulp(X[k], Y[k], f0); cmulp(X[k + n], Y[k + n], f1);
            }
        }
    }

    // ======== layers 1..5: ring first, then gates; final ring folded into readout
#pragma unroll 1
    for (int layer = 1; layer < 6; layer++) {
        ring(X, Y, srcLo, srcHi, c0);

        C au, bu, myga, mygb;
        buildRot(weights + layer * 30 + myw * 3, au, bu);
        buildG(au, bu, ag, myBg, myga, mygb);

#pragma unroll
        for (int w = 0; w < 10; w++) {
            const float gax = __shfl_sync(FULL, myga.x, w);
            const float gay = __shfl_sync(FULL, myga.y, w);
            const float gbx = __shfl_sync(FULL, mygb.x, w);
            const float gby = __shfl_sync(FULL, mygb.y, w);

            if (w <= 3) {
                const int ks = 8 >> w;
                const u64 paxx = B2(gax), pnay = B2(-gay), ppay = B2(gay);
                const u64 pbxx = B2(gbx), pnbx = B2(-gbx);
                const u64 pnby = B2(-gby), ppby = B2(gby);
#pragma unroll
                for (int kl = 0; kl < 16; kl++) {
                    if (kl & ks) continue;
                    const int kh = kl | ks;
                    u64 Xl = X[kl], Yl = Y[kl], Xh = X[kh], Yh = Y[kh];
                    X[kl] = F2(paxx, Xl, F2(pnay, Yl, F2(pbxx, Xh, M2(pnby, Yh))));
                    Y[kl] = F2(paxx, Yl, F2(ppay, Xl, F2(pbxx, Yh, M2(ppby, Xh))));
                    X[kh] = F2(paxx, Xh, F2(ppay, Yh, F2(pnbx, Xl, M2(pnby, Yl))));
                    Y[kh] = F2(paxx, Yh, F2(pnay, Xh, F2(pnbx, Yl, M2(ppby, Xl))));
                }
            } else if (w == 4) {
                const u64 qaxx = B2(gax);
                const u64 qay  = PK(-gay,  gay);
                const u64 qay2 = PK( gay, -gay);
                const u64 qbx  = PK( gbx, -gbx);
                const u64 qnby = B2(-gby), qpby = B2(gby);
#pragma unroll
                for (int k = 0; k < 16; k++) {
                    u64 ownX = F2(qaxx, X[k], M2(qay,  Y[k]));
                    u64 ownY = F2(qaxx, Y[k], M2(qay2, X[k]));
                    u64 Xs = SW64(X[k]), Ys = SW64(Y[k]);
                    u64 nX = F2(qbx, Xs, F2(qnby, Ys, ownX));
                    u64 nY = F2(qbx, Ys, F2(qpby, Xs, ownY));
                    X[k] = nX; Y[k] = nY;
                }
            } else {
                const int m = 1 << (9 - w);
                const bool hib = (lane & m) != 0;
                const float aly = hib ? -gay : gay;
                const float bex = hib ? -gbx : gbx;
                const u64 pA   = B2(gax);
                const u64 pAy  = B2(aly),  pnAy = B2(-aly);
                const u64 pBx  = B2(bex);
                const u64 pBy  = B2(gby), pnBy = B2(-gby);
#pragma unroll
                for (int k = 0; k < 16; k++) {
                    u64 ownX = F2(pA, X[k], M2(pnAy, Y[k]));
                    u64 ownY = F2(pA, Y[k], M2(pAy,  X[k]));
                    u64 OX = SHX64(X[k], m), OY = SHX64(Y[k], m);
                    u64 nX = F2(pBx, OX, F2(pnBy, OY, ownX));
                    u64 nY = F2(pBx, OY, F2(pBy,  OX, ownY));
                    X[k] = nX; Y[k] = nY;
                }
            }
        }
    }

    // ---- readout with final CNOT ring folded in ----
    // coef_w(i) = (-1)^{parity(M_w & i)}, M_w = row_{9-w}(R):
    //   M_0 = 0x1FF;  M_w = 0x3FF & ~((1<<(9-w))-1)  for w>=1.
    float pw[10];
#pragma unroll
    for (int w = 0; w < 10; w++) pw[w] = post_W[w];

    const float t0 = (__popc(lane & 0x1F) & 1) ? -pw[0] : pw[0];
    const float t5 = (__popc(lane & 0x10) & 1) ? -pw[5] : pw[5];
    const float t6 = (__popc(lane & 0x18) & 1) ? -pw[6] : pw[6];
    const float t7 = (__popc(lane & 0x1C) & 1) ? -pw[7] : pw[7];
    const float t8 = (__popc(lane & 0x1E) & 1) ? -pw[8] : pw[8];
    const float t9 = (__popc(lane & 0x1F) & 1) ? -pw[9] : pw[9];
    const float S  = pw[4] + t5 + t6 + t7 + t8 + t9;
    const float Pp = pw[3] + S;
    const float Qm = pw[3] - S;

    u64 acc2 = 0ull;
#pragma unroll
    for (int k = 0; k < 16; k++) {
        const float s1 = par4(k & 12) ? -1.f : 1.f;
        const float s2 = par4(k & 14) ? -1.f : 1.f;
        const float sp = par4(k)      ? -1.f : 1.f;
        const float s0 = par4(k & 7)  ? -1.f : 1.f;
        const float common = s1 * pw[1] + s2 * pw[2];
        const float lo = common + sp * Pp + s0 * t0;
        const float hi = common + sp * Qm - s0 * t0;
        const u64 cp = PK(lo, hi);
        const u64 p2 = F2(X[k], X[k], M2(Y[k], Y[k]));
        acc2 = F2(p2, cp, acc2);
    }
    float aLo, aHi;
    UPK(acc2, aLo, aHi);
    float acc = aLo + aHi;

#pragma unroll
    for (int off = 16; off; off >>= 1)
        acc += __shfl_xor_sync(FULL, acc, off);

    if (lane == 0)
        out[samp] = readout[0] * (acc + post_b[0]) + bias[0];
}

extern "C" void kernel_launch(void* const* d_in, const int* in_sizes, int n_in,
                              void* d_out, int out_size)
{
    const float* x       = (const float*)d_in[0];
    const float* weights = (const float*)d_in[1];
    const float* post_W  = (const float*)d_in[2];
    const float* post_b  = (const float*)d_in[3];
    const float* readout = (const float*)d_in[4];
    const float* bias    = (const float*)d_in[5];
    float* out = (float*)d_out;

    const int batch = in_sizes[0] / 2;
    const int threads = 256;   // 8 warps/block, 2 blocks/SM -> 16 warps/SM
    const int total_threads = batch * 32;
    const int blocks = (total_threads + threads - 1) / threads;
    qsim_kernel<<<blocks, threads>>>(x, weights, post_W, post_b, readout, bias, out, batch);
}

// round 16
// speedup vs baseline: 1.1213x; 1.0019x over previous
#include <cuda_runtime.h>

#define FULL 0xffffffffu

typedef unsigned long long u64;

struct C { float x, y; };

// ---------- f32x2 packed helpers ----------
__device__ __forceinline__ u64 PK(float lo, float hi) {
    u64 r;
    asm("mov.b64 %0, {%1, %2};" : "=l"(r)
        : "r"(__float_as_uint(lo)), "r"(__float_as_uint(hi)));
    return r;
}
__device__ __forceinline__ void UPK(u64 p, float& lo, float& hi) {
    unsigned a, b;
    asm("mov.b64 {%0, %1}, %2;" : "=r"(a), "=r"(b) : "l"(p));
    lo = __uint_as_float(a); hi = __uint_as_float(b);
}
__device__ __forceinline__ u64 F2(u64 a, u64 b, u64 c) {
    u64 d;
    asm("fma.rn.f32x2 %0, %1, %2, %3;" : "=l"(d) : "l"(a), "l"(b), "l"(c));
    return d;
}
__device__ __forceinline__ u64 M2(u64 a, u64 b) {
    u64 d;
    asm("mul.rn.f32x2 %0, %1, %2;" : "=l"(d) : "l"(a), "l"(b));
    return d;
}
__device__ __forceinline__ u64 B2(float v) { return PK(v, v); }
__device__ __forceinline__ u64 SW64(u64 p) { float l, h; UPK(p, l, h); return PK(h, l); }
__device__ __forceinline__ u64 SHX64(u64 p, int m) {
    float l, h; UPK(p, l, h);
    return PK(__shfl_xor_sync(FULL, l, m), __shfl_xor_sync(FULL, h, m));
}
__device__ __forceinline__ C cmul(C a, C b) {
    C r;
    r.x = fmaf(a.x, b.x, -a.y * b.y);
    r.y = fmaf(a.x, b.y,  a.y * b.x);
    return r;
}
__device__ __forceinline__ void cmulp(u64& X, u64& Y, C c) {
    u64 cx = B2(c.x), cy = B2(c.y), ny = B2(-c.y);
    u64 nX = F2(cx, X, M2(ny, Y));
    u64 nY = F2(cx, Y, M2(cy, X));
    X = nX; Y = nY;
}

// Rot gate (SU(2)) from raw weights: a = e^{-i(phi+om)/2} cos(th/2), b = -e^{i(phi-om)/2} sin(th/2)
__device__ __forceinline__ void buildRot(const float* __restrict__ wl, C& au, C& bu) {
    const float phi = wl[0], th = wl[1], om = wl[2];
    float st, ct, sa, ca, sb, cb;
    __sincosf(0.5f * th,         &st, &ct);
    __sincosf(0.5f * (phi + om), &sa, &ca);
    __sincosf(0.5f * (phi - om), &sb, &cb);
    au = C{ ca * ct, -sa * ct };
    bu = C{ -cb * st, -sb * st };
}

// fused gate coefficients: M = Rot * (RY*RX) in SU(2) form {ga, gb}
__device__ __forceinline__ void buildG(C au, C bu, C ag, C bg, C& ga, C& gb) {
    ga.x = fmaf(au.x, ag.x, fmaf(-au.y, ag.y, fmaf(-bu.x, bg.x, -bu.y * bg.y)));
    ga.y = fmaf(au.x, ag.y, fmaf( au.y, ag.x, fmaf(-bu.y, bg.x,  bu.x * bg.y)));
    gb.x = fmaf(au.x, bg.x, fmaf(-au.y, bg.y, fmaf( bu.x, ag.x,  bu.y * ag.y)));
    gb.y = fmaf(au.x, bg.y, fmaf( au.y, bg.x, fmaf( bu.y, ag.x, -bu.x * ag.y)));
}

// ---------- CNOT ring on packed state ----------
__device__ __forceinline__ void ring(u64 (&X)[16], u64 (&Y)[16],
                                     int srcLo, int srcHi, bool c0) {
#pragma unroll
    for (int k = 0; k < 16; k++)
        if ((k & 8) && !(k & 4)) { u64 t = X[k]; X[k] = X[k ^ 4]; X[k ^ 4] = t;
                                   t = Y[k]; Y[k] = Y[k ^ 4]; Y[k ^ 4] = t; }
#pragma unroll
    for (int k = 0; k < 16; k++)
        if ((k & 4) && !(k & 2)) { u64 t = X[k]; X[k] = X[k ^ 2]; X[k ^ 2] = t;
                                   t = Y[k]; Y[k] = Y[k ^ 2]; Y[k ^ 2] = t; }
#pragma unroll
    for (int k = 0; k < 16; k++)
        if ((k & 2) && !(k & 1)) { u64 t = X[k]; X[k] = X[k ^ 1]; X[k ^ 1] = t;
                                   t = Y[k]; Y[k] = Y[k ^ 1]; Y[k ^ 1] = t; }
#pragma unroll
    for (int k = 0; k < 16; k++) {
        float xl, xh, yl, yh;
        UPK(X[k], xl, xh); UPK(Y[k], yl, yh);
        float nxl, nxh, nyl, nyh;
        if (k & 1) {
            nxl = __shfl_sync(FULL, xh, srcLo); nxh = __shfl_sync(FULL, xl, srcHi);
            nyl = __shfl_sync(FULL, yh, srcLo); nyh = __shfl_sync(FULL, yl, srcHi);
        } else {
            nxl = __shfl_sync(FULL, xl, srcLo); nxh = __shfl_sync(FULL, xh, srcHi);
            nyl = __shfl_sync(FULL, yl, srcLo); nyh = __shfl_sync(FULL, yh, srcHi);
        }
        X[k] = PK(nxl, nxh); Y[k] = PK(nyl, nyh);
    }
#pragma unroll
    for (int k = 0; k < 8; k++) {
        u64 a = X[k], d = X[k + 8];
        X[k] = c0 ? d : a; X[k + 8] = c0 ? a : d;
        a = Y[k]; d = Y[k + 8];
        Y[k] = c0 ? d : a; Y[k + 8] = c0 ? a : d;
    }
}

// compile-time parity helper
__host__ __device__ constexpr int par4(int v) { return ((v >> 3) ^ (v >> 2) ^ (v >> 1) ^ v) & 1; }

// ===================== main kernel =====================
// amplitude i = (k<<6) | (h<<5) | lane; X[k] packs {Re(h=0),Re(h=1)}, Y imag.
// wire w <-> bit 9-w: w0..w3 -> pack bits 3..0, w4 -> half h, w5..w9 -> lane bits 4..0.
__global__ void __launch_bounds__(256, 2)
qsim_kernel(const float* __restrict__ x,
            const float* __restrict__ weights,
            const float* __restrict__ post_W,
            const float* __restrict__ post_b,
            const float* __restrict__ readout,
            const float* __restrict__ bias,
            float* __restrict__ out,
            int batch)
{
    const int lane = threadIdx.x & 31;
    const int samp = (int)((blockIdx.x * blockDim.x + threadIdx.x) >> 5);
    if (samp >= batch) return;

    const float x0 = x[2 * samp + 0];
    const float x1 = x[2 * samp + 1];
    float sx0, cx0, sx1, cx1;
    __sincosf(0.5f * x0, &sx0, &cx0);
    __sincosf(0.5f * x1, &sx1, &cx1);

    const C ag   { cx1 * cx0,  sx1 * sx0 };
    const C bg_e { -sx1 * cx0, -cx1 * sx0 };  // even wires: RX(x0), RY(x1)
    const C bg_o { -sx0 * cx1, -cx0 * sx1 };  // odd  wires: RX(x1), RY(x0)

    int gsrc = lane;
    gsrc = (gsrc & 2)  ? (gsrc ^ 1) : gsrc;
    gsrc = (gsrc & 4)  ? (gsrc ^ 2) : gsrc;
    gsrc = (gsrc & 8)  ? (gsrc ^ 4) : gsrc;
    gsrc = (gsrc & 16) ? (gsrc ^ 8) : gsrc;
    const int srcLo = gsrc, srcHi = gsrc ^ 16;
    const bool c0 = (lane & 1) != 0;

    // Which gate this lane builds; lanes >= 10 duplicate gate 9.
    const int myw = lane < 10 ? lane : 9;
    const C myBg = (myw & 1) ? bg_o : bg_e;

    u64 X[16], Y[16];

    // ======== layer 0: product state; distributed builds + broadcasts ========
    C curA, curB;   // this layer's gate coefficients (lane myw owns gate myw)
    {
        C au, bu;
        buildRot(weights + myw * 3, au, bu);
        buildG(au, bu, ag, myBg, curA, curB);

        // lane factor: wires 5..9 selected by lane bits 4..0
        C Lc;
        {
            const float gax = __shfl_sync(FULL, curA.x, 5);
            const float gay = __shfl_sync(FULL, curA.y, 5);
            const float gbx = __shfl_sync(FULL, curB.x, 5);
            const float gby = __shfl_sync(FULL, curB.y, 5);
            Lc = ((lane >> 4) & 1) ? C{-gbx, gby} : C{gax, gay};
        }
#pragma unroll
        for (int wv = 6; wv <= 9; wv++) {
            const float gax = __shfl_sync(FULL, curA.x, wv);
            const float gay = __shfl_sync(FULL, curA.y, wv);
            const float gbx = __shfl_sync(FULL, curB.x, wv);
            const float gby = __shfl_sync(FULL, curB.y, wv);
            const C f = ((lane >> (9 - wv)) & 1) ? C{-gbx, gby} : C{gax, gay};
            Lc = cmul(Lc, f);
        }
        // half factor (wire 4)
        {
            const float gax = __shfl_sync(FULL, curA.x, 4);
            const float gay = __shfl_sync(FULL, curA.y, 4);
            const float gbx = __shfl_sync(FULL, curB.x, 4);
            const float gby = __shfl_sync(FULL, curB.y, 4);
            C h0 = cmul(Lc, C{gax, gay});
            C h1 = cmul(Lc, C{-gbx, gby});
            X[0] = PK(h0.x, h1.x);
            Y[0] = PK(h0.y, h1.y);
        }
        // tensor tree over pack bits: bit0=wire3, bit1=wire2, bit2=wire1, bit3=wire0
#pragma unroll
        for (int wv = 3; wv >= 0; wv--) {
            const float gax = __shfl_sync(FULL, curA.x, wv);
            const float gay = __shfl_sync(FULL, curA.y, wv);
            const float gbx = __shfl_sync(FULL, curB.x, wv);
            const float gby = __shfl_sync(FULL, curB.y, wv);
            const C f0{gax, gay}, f1{-gbx, gby};
            const int n = 1 << (3 - wv);
#pragma unroll
            for (int k = 0; k < 8; k++) {
                if (k >= n) break;
                X[k + n] = X[k]; Y[k + n] = Y[k];
                cmulp(X[k], Y[k], f0); cmulp(X[k + n], Y[k + n], f1);
            }
        }
        // prefetch layer 1's gate coefficients
        buildRot(weights + 30 + myw * 3, au, bu);
        buildG(au, bu, ag, myBg, curA, curB);
    }

    // ======== layers 1..5: ring, gates (with next-layer build pipelined) ========
#pragma unroll 1
    for (int layer = 1; layer < 6; layer++) {
        ring(X, Y, srcLo, srcHi, c0);

        // Pipelined build of NEXT layer's coefficients (independent of state;
        // scheduler fills butterfly stall slots). Last iteration redoes layer 5
        // (result unused) to stay branchless.
        const int nl = (layer < 5) ? layer + 1 : 5;
        C nau, nbu, nxtA, nxtB;
        buildRot(weights + nl * 30 + myw * 3, nau, nbu);
        buildG(nau, nbu, ag, myBg, nxtA, nxtB);

#pragma unroll
        for (int w = 0; w < 10; w++) {
            const float gax = __shfl_sync(FULL, curA.x, w);
            const float gay = __shfl_sync(FULL, curA.y, w);
            const float gbx = __shfl_sync(FULL, curB.x, w);
            const float gby = __shfl_sync(FULL, curB.y, w);

            if (w <= 3) {
                const int ks = 8 >> w;
                const u64 paxx = B2(gax), pnay = B2(-gay), ppay = B2(gay);
                const u64 pbxx = B2(gbx), pnbx = B2(-gbx);
                const u64 pnby = B2(-gby), ppby = B2(gby);
#pragma unroll
                for (int kl = 0; kl < 16; kl++) {
                    if (kl & ks) continue;
                    const int kh = kl | ks;
                    u64 Xl = X[kl], Yl = Y[kl], Xh = X[kh], Yh = Y[kh];
                    X[kl] = F2(paxx, Xl, F2(pnay, Yl, F2(pbxx, Xh, M2(pnby, Yh))));
                    Y[kl] = F2(paxx, Yl, F2(ppay, Xl, F2(pbxx, Yh, M2(ppby, Xh))));
                    X[kh] = F2(paxx, Xh, F2(ppay, Yh, F2(pnbx, Xl, M2(pnby, Yl))));
                    Y[kh] = F2(paxx, Yh, F2(pnay, Xh, F2(pnbx, Yl, M2(ppby, Xl))));
                }
            } else if (w == 4) {
                const u64 qaxx = B2(gax);
                const u64 qay  = PK(-gay,  gay);
                const u64 qay2 = PK( gay, -gay);
                const u64 qbx  = PK( gbx, -gbx);
                const u64 qnby = B2(-gby), qpby = B2(gby);
#pragma unroll
                for (int k = 0; k < 16; k++) {
                    u64 ownX = F2(qaxx, X[k], M2(qay,  Y[k]));
                    u64 ownY = F2(qaxx, Y[k], M2(qay2, X[k]));
                    u64 Xs = SW64(X[k]), Ys = SW64(Y[k]);
                    u64 nX = F2(qbx, Xs, F2(qnby, Ys, ownX));
                    u64 nY = F2(qbx, Ys, F2(qpby, Xs, ownY));
                    X[k] = nX; Y[k] = nY;
                }
            } else {
                const int m = 1 << (9 - w);
                const bool hib = (lane & m) != 0;
                const float aly = hib ? -gay : gay;
                const float bex = hib ? -gbx : gbx;
                const u64 pA   = B2(gax);
                const u64 pAy  = B2(aly),  pnAy = B2(-aly);
                const u64 pBx  = B2(bex);
                const u64 pBy  = B2(gby), pnBy = B2(-gby);
#pragma unroll
                for (int k = 0; k < 16; k++) {
                    u64 ownX = F2(pA, X[k], M2(pnAy, Y[k]));
                    u64 ownY = F2(pA, Y[k], M2(pAy,  X[k]));
                    u64 OX = SHX64(X[k], m), OY = SHX64(Y[k], m);
                    u64 nX = F2(pBx, OX, F2(pnBy, OY, ownX));
                    u64 nY = F2(pBx, OY, F2(pBy,  OX, ownY));
                    X[k] = nX; Y[k] = nY;
                }
            }
        }

        curA = nxtA; curB = nxtB;
    }

    // ---- readout with final CNOT ring folded in ----
    // coef_w(i) = (-1)^{parity(M_w & i)}, M_w = row_{9-w}(R):
    //   M_0 = 0x1FF;  M_w = 0x3FF & ~((1<<(9-w))-1)  for w>=1.
    float pw[10];
#pragma unroll
    for (int w = 0; w < 10; w++) pw[w] = post_W[w];

    const float t0 = (__popc(lane & 0x1F) & 1) ? -pw[0] : pw[0];
    const float t5 = (__popc(lane & 0x10) & 1) ? -pw[5] : pw[5];
    const float t6 = (__popc(lane & 0x18) & 1) ? -pw[6] : pw[6];
    const float t7 = (__popc(lane & 0x1C) & 1) ? -pw[7] : pw[7];
    const float t8 = (__popc(lane & 0x1E) & 1) ? -pw[8] : pw[8];
    const float t9 = (__popc(lane & 0x1F) & 1) ? -pw[9] : pw[9];
    const float S  = pw[4] + t5 + t6 + t7 + t8 + t9;
    const float Pp = pw[3] + S;
    const float Qm = pw[3] - S;

    u64 acc2 = 0ull;
#pragma unroll
    for (int k = 0; k < 16; k++) {
        const float s1 = par4(k & 12) ? -1.f : 1.f;
        const float s2 = par4(k & 14) ? -1.f : 1.f;
        const float sp = par4(k)      ? -1.f : 1.f;
        const float s0 = par4(k & 7)  ? -1.f : 1.f;
        const float common = s1 * pw[1] + s2 * pw[2];
        const float lo = common + sp * Pp + s0 * t0;
        const float hi = common + sp * Qm - s0 * t0;
        const u64 cp = PK(lo, hi);
        const u64 p2 = F2(X[k], X[k], M2(Y[k], Y[k]));
        acc2 = F2(p2, cp, acc2);
    }
    float aLo, aHi;
    UPK(acc2, aLo, aHi);
    float acc = aLo + aHi;

#pragma unroll
    for (int off = 16; off; off >>= 1)
        acc += __shfl_xor_sync(FULL, acc, off);

    if (lane == 0)
        out[samp] = readout[0] * (acc + post_b[0]) + bias[0];
}

extern "C" void kernel_launch(void* const* d_in, const int* in_sizes, int n_in,
                              void* d_out, int out_size)
{
    const float* x       = (const float*)d_in[0];
    const float* weights = (const float*)d_in[1];
    const float* post_W  = (const float*)d_in[2];
    const float* post_b  = (const float*)d_in[3];
    const float* readout = (const float*)d_in[4];
    const float* bias    = (const float*)d_in[5];
    float* out = (float*)d_out;

    const int batch = in_sizes[0] / 2;
    const int threads = 256;   // 8 warps/block, 2 blocks/SM -> 16 warps/SM
    const int total_threads = batch * 32;
    const int blocks = (total_threads + threads - 1) / threads;
    qsim_kernel<<<blocks, threads>>>(x, weights, post_W, post_b, readout, bias, out, batch);
}